// round 5
// baseline (speedup 1.0000x reference)
#include <cuda_runtime.h>

// Problem constants
#define N_    64
#define C_    64
#define T_    300
#define V_    25
#define IC_   16
#define NS_   3
#define TC_   12           // t-values per block
#define COLS_ 300          // TC_ * V_
#define NTHREADS 320
#define NCHUNKS (N_ * (T_ / TC_))   // 64 * 25 = 1600

typedef unsigned long long ull;

__device__ __forceinline__ ull dup2(float v) {
    ull r; asm("mov.b64 %0, {%1, %1};" : "=l"(r) : "f"(v)); return r;
}
__device__ __forceinline__ void fma2(ull& acc, ull a, ull b) {
    asm("fma.rn.f32x2 %0, %1, %2, %0;" : "+l"(acc) : "l"(a), "l"(b));
}
__device__ __forceinline__ ull mul2(ull a, ull b) {
    ull d; asm("mul.rn.f32x2 %0, %1, %2;" : "=l"(d) : "l"(a), "l"(b)); return d;
}
__device__ __forceinline__ void unpack2(ull v, float& lo, float& hi) {
    asm("mov.b64 {%0, %1}, %2;" : "=f"(lo), "=f"(hi) : "l"(v));
}

struct Smem {
    float WabT[NS_][64][32];      // [s][c][r] r<16: a_w, r>=16: b_w       24576 B
    float GT[NS_][64][64];        // [s][c][o]                             49152 B
    float xs[64][COLS_];          // [c][col]                              76800 B
    float CaCb[32][TC_ * 28];     // [r][tc*28+v]                          43008 B
    float Pm[TC_][25][26];        // softmax probs                         31200 B
    float Msh[NS_][COLS_];       // M per subset/col                       3600 B
    float colA[NS_][32];
    float absh[NS_][32];
    float scArr[64];
    float shArr[64];
};

__global__ void __launch_bounds__(NTHREADS, 1)
tsagc_kernel(const float* __restrict__ x,
             const float* __restrict__ A,
             const float* __restrict__ GA,
             const float* __restrict__ g_w,
             const float* __restrict__ g_b,
             const float* __restrict__ a_w,
             const float* __restrict__ a_b,
             const float* __restrict__ b_w,
             const float* __restrict__ b_b,
             const float* __restrict__ bn_gamma,
             const float* __restrict__ bn_beta,
             const float* __restrict__ bn_mean,
             const float* __restrict__ bn_var,
             float* __restrict__ out)
{
    extern __shared__ float smem_raw[];
    Smem& sm = *reinterpret_cast<Smem*>(smem_raw);
    const int tid = threadIdx.x;

    // ---------------- Phase 0: stage weights / constants ----------------
    for (int idx = tid; idx < NS_ * IC_ * 64; idx += NTHREADS) {
        int c  = idx & 63;
        int ic = (idx >> 6) & 15;
        int s  = idx >> 10;
        sm.WabT[s][c][ic]      = a_w[idx];
        sm.WabT[s][c][16 + ic] = b_w[idx];
    }
    for (int idx = tid; idx < NS_ * 64 * 64; idx += NTHREADS) {
        int c = idx & 63;
        int o = (idx >> 6) & 63;
        int s = idx >> 12;
        sm.GT[s][c][o] = g_w[idx];
    }
    if (tid < 64) {
        float inv = rsqrtf(bn_var[tid] + 1e-5f);
        float scv = bn_gamma[tid] * inv;
        sm.scArr[tid] = scv;
        float cb = g_b[tid] + g_b[64 + tid] + g_b[128 + tid];
        sm.shArr[tid] = (cb - bn_mean[tid]) * scv + bn_beta[tid];
    }
    for (int idx = tid; idx < NS_ * IC_; idx += NTHREADS) {
        int s = idx / IC_, ic = idx % IC_;
        sm.absh[s][ic]      = a_b[idx];
        sm.absh[s][16 + ic] = b_b[idx];
    }
    for (int idx = tid; idx < NS_ * V_; idx += NTHREADS) {
        int s = idx / V_, v = idx % V_;
        float acc = 0.f;
        #pragma unroll 5
        for (int a = 0; a < V_; a++) {
            int off = (s * V_ + a) * V_ + v;
            acc += A[off] + GA[off];
        }
        sm.colA[s][v] = acc;
    }
    // zero CaCb pad columns (v=25..27) so vector pair loads never see garbage
    for (int idx = tid; idx < 32 * TC_ * 3; idx += NTHREADS) {
        int r = idx / (TC_ * 3);
        int q = idx % (TC_ * 3);
        sm.CaCb[r][(q / 3) * 28 + 25 + (q % 3)] = 0.f;
    }

    // ---------------- Load x chunk ----------------
    const int chunk = blockIdx.x;
    const int n  = chunk / (T_ / TC_);
    const int t0 = (chunk % (T_ / TC_)) * TC_;
    const float* xg = x + (n * 64 * T_ + t0) * V_;
    for (int idx = tid; idx < 64 * (COLS_ / 4); idx += NTHREADS) {
        int c = idx / (COLS_ / 4), q = idx % (COLS_ / 4);
        float4 val = *reinterpret_cast<const float4*>(xg + c * (T_ * V_) + q * 4);
        *reinterpret_cast<float4*>(&sm.xs[c][q * 4]) = val;
    }
    __syncthreads();

    // GEMM thread mapping (tid < 300): 4 row-groups x 75 col-groups, 4 cols each
    const int rg   = tid / 75;        // 0..3
    const int cg   = tid % 75;        // 0..74
    const int col0 = cg * 4;          // 16B-aligned column base

    int tcv[4], vv[4];
    #pragma unroll
    for (int j = 0; j < 4; j++) {
        int col = col0 + j;
        tcv[j] = col / 25;
        vv[j]  = col - tcv[j] * 25;
    }

    // =========== Phases 1+2 per subset: produce Msh[s][*] ===========
    for (int s = 0; s < NS_; s++) {
        // ---- Phase 1: CaCb[32][300] = Wab[s] @ xs  (8x4 tiles, f32x2) ----
        if (tid < 300) {
            const int r0 = rg * 8;
            ull acc2[8][2];
            #pragma unroll
            for (int k = 0; k < 8; k++) { acc2[k][0] = 0ull; acc2[k][1] = 0ull; }
            #pragma unroll 2
            for (int c = 0; c < 64; c++) {
                float4 w0 = *reinterpret_cast<const float4*>(&sm.WabT[s][c][r0]);
                float4 w1 = *reinterpret_cast<const float4*>(&sm.WabT[s][c][r0 + 4]);
                ulonglong2 xv = *reinterpret_cast<const ulonglong2*>(&sm.xs[c][col0]);
                float wa[8] = {w0.x, w0.y, w0.z, w0.w, w1.x, w1.y, w1.z, w1.w};
                #pragma unroll
                for (int k = 0; k < 8; k++) {
                    ull wd = dup2(wa[k]);
                    fma2(acc2[k][0], wd, xv.x);
                    fma2(acc2[k][1], wd, xv.y);
                }
            }
            #pragma unroll
            for (int k = 0; k < 8; k++) {
                float bias = sm.absh[s][r0 + k];
                float v0, v1, v2, v3;
                unpack2(acc2[k][0], v0, v1);
                unpack2(acc2[k][1], v2, v3);
                float vals[4] = {v0, v1, v2, v3};
                #pragma unroll
                for (int j = 0; j < 4; j++)
                    sm.CaCb[r0 + k][tcv[j] * 28 + vv[j]] = vals[j] + bias;
            }
        }
        __syncthreads();

        // ---- Phase 2a: logits + softmax, 2 rows per thread (156 threads) ----
        if (tid < 156) {
            const int tc = tid / 13, a0 = tid % 13;
            const int a1 = a0 + 13;
            const bool has2 = (a1 < 25);
            const int tcBase = tc * 28;
            ull lA[13], lB[13];
            #pragma unroll
            for (int p = 0; p < 13; p++) { lA[p] = 0ull; lB[p] = 0ull; }
            #pragma unroll 4
            for (int ic = 0; ic < 16; ic++) {
                ull cad0 = dup2(sm.CaCb[ic][tcBase + a0]);
                ull cad1 = has2 ? dup2(sm.CaCb[ic][tcBase + a1]) : 0ull;
                const ulonglong2* cb =
                    reinterpret_cast<const ulonglong2*>(&sm.CaCb[16 + ic][tcBase]);
                #pragma unroll
                for (int q = 0; q < 6; q++) {
                    ulonglong2 cv = cb[q];
                    fma2(lA[q * 2],     cad0, cv.x);
                    fma2(lA[q * 2 + 1], cad0, cv.y);
                    fma2(lB[q * 2],     cad1, cv.x);
                    fma2(lB[q * 2 + 1], cad1, cv.y);
                }
                ulonglong2 cv6 = cb[6];
                fma2(lA[12], cad0, cv6.x);
                fma2(lB[12], cad1, cv6.x);
            }
            // softmax row a0
            {
                float l[26];
                #pragma unroll
                for (int p = 0; p < 13; p++) unpack2(lA[p], l[2 * p], l[2 * p + 1]);
                float mx = -1e30f;
                #pragma unroll
                for (int b = 0; b < 25; b++) { l[b] *= 0.0625f; mx = fmaxf(mx, l[b]); }
                float ssum = 0.f;
                #pragma unroll
                for (int b = 0; b < 25; b++) { float e = __expf(l[b] - mx); ssum += e; l[b] = e; }
                float inv = 1.f / ssum;
                float* pr = sm.Pm[tc][a0];
                #pragma unroll
                for (int b = 0; b < 25; b++) pr[b] = l[b] * inv;
            }
            if (has2) {
                float l[26];
                #pragma unroll
                for (int p = 0; p < 13; p++) unpack2(lB[p], l[2 * p], l[2 * p + 1]);
                float mx = -1e30f;
                #pragma unroll
                for (int b = 0; b < 25; b++) { l[b] *= 0.0625f; mx = fmaxf(mx, l[b]); }
                float ssum = 0.f;
                #pragma unroll
                for (int b = 0; b < 25; b++) { float e = __expf(l[b] - mx); ssum += e; l[b] = e; }
                float inv = 1.f / ssum;
                float* pr = sm.Pm[tc][a1];
                #pragma unroll
                for (int b = 0; b < 25; b++) pr[b] = l[b] * inv;
            }
        }
        __syncthreads();

        // ---- Phase 2b: column sums -> Msh[s] ----
        if (tid < 300) {
            const int tc = tid / 25, b = tid % 25;
            float msum = sm.colA[s][b];
            #pragma unroll 5
            for (int a = 0; a < 25; a++) msum += sm.Pm[tc][a][b];
            sm.Msh[s][tc * 25 + b] = msum;
        }
        __syncthreads();
    }

    // =========== Phase 3 (fused over subsets): 16x4 tiles, f32x2 ===========
    if (tid < 300) {
        const int o0 = rg * 16;
        ull acc2[16][2];
        #pragma unroll
        for (int k = 0; k < 16; k++) { acc2[k][0] = 0ull; acc2[k][1] = 0ull; }

        ull m2[NS_][2];
        #pragma unroll
        for (int s = 0; s < NS_; s++) {
            ulonglong2 mv = *reinterpret_cast<const ulonglong2*>(&sm.Msh[s][col0]);
            m2[s][0] = mv.x; m2[s][1] = mv.y;
        }

        #pragma unroll 2
        for (int c = 0; c < 64; c++) {
            ulonglong2 xv = *reinterpret_cast<const ulonglong2*>(&sm.xs[c][col0]);
            #pragma unroll
            for (int s = 0; s < NS_; s++) {
                float4 g0 = *reinterpret_cast<const float4*>(&sm.GT[s][c][o0]);
                float4 g1 = *reinterpret_cast<const float4*>(&sm.GT[s][c][o0 + 4]);
                float4 g2 = *reinterpret_cast<const float4*>(&sm.GT[s][c][o0 + 8]);
                float4 g3 = *reinterpret_cast<const float4*>(&sm.GT[s][c][o0 + 12]);
                float ga[16] = {g0.x, g0.y, g0.z, g0.w, g1.x, g1.y, g1.z, g1.w,
                                g2.x, g2.y, g2.z, g2.w, g3.x, g3.y, g3.z, g3.w};
                ull xm0 = mul2(xv.x, m2[s][0]);
                ull xm1 = mul2(xv.y, m2[s][1]);
                #pragma unroll
                for (int k = 0; k < 16; k++) {
                    ull gd = dup2(ga[k]);
                    fma2(acc2[k][0], gd, xm0);
                    fma2(acc2[k][1], gd, xm1);
                }
            }
        }

        // ---------------- Epilogue: BN + residual + ReLU ----------------
        #pragma unroll
        for (int k = 0; k < 16; k++) {
            int o = o0 + k;
            float scv = sm.scArr[o];
            float shv = sm.shArr[o];
            float4 xr = *reinterpret_cast<const float4*>(&sm.xs[o][col0]);
            float a0v, a1v, a2v, a3v;
            unpack2(acc2[k][0], a0v, a1v);
            unpack2(acc2[k][1], a2v, a3v);
            float4 res;
            res.x = fmaxf(a0v * scv + shv + xr.x, 0.f);
            res.y = fmaxf(a1v * scv + shv + xr.y, 0.f);
            res.z = fmaxf(a2v * scv + shv + xr.z, 0.f);
            res.w = fmaxf(a3v * scv + shv + xr.w, 0.f);
            float* op = out + (n * 64 + o) * (T_ * V_) + t0 * V_ + col0;
            *reinterpret_cast<float4*>(op) = res;
        }
    }
}

extern "C" void kernel_launch(void* const* d_in, const int* in_sizes, int n_in,
                              void* d_out, int out_size)
{
    const float* x        = (const float*)d_in[0];
    const float* A        = (const float*)d_in[1];
    const float* GA       = (const float*)d_in[2];
    const float* g_w      = (const float*)d_in[3];
    const float* g_b      = (const float*)d_in[4];
    const float* a_w      = (const float*)d_in[5];
    const float* a_b      = (const float*)d_in[6];
    const float* b_w      = (const float*)d_in[7];
    const float* b_b      = (const float*)d_in[8];
    const float* bn_gamma = (const float*)d_in[9];
    const float* bn_beta  = (const float*)d_in[10];
    const float* bn_mean  = (const float*)d_in[11];
    const float* bn_var   = (const float*)d_in[12];
    float* out = (float*)d_out;

    size_t smem = sizeof(Smem);
    cudaFuncSetAttribute(tsagc_kernel,
                         cudaFuncAttributeMaxDynamicSharedMemorySize, (int)smem);
    tsagc_kernel<<<NCHUNKS, NTHREADS, smem>>>(
        x, A, GA, g_w, g_b, a_w, a_b, b_w, b_b,
        bn_gamma, bn_beta, bn_mean, bn_var, out);
}